// round 1
// baseline (speedup 1.0000x reference)
#include <cuda_runtime.h>

// 7x7 exact median blur, zero padding, NCHW 8x3x512x512 fp32.
// Forgetful selection: start with 26 window values; the min and max of any
// 26-subset of 49 cannot be the rank-25 (1-based) element. Discard both,
// stream in one new value, repeat (set shrinks 26 -> 3), median = mid of 3.
// All indices are compile-time constants (template recursion) so the working
// set stays in registers.

#define IMG_H 512
#define IMG_W 512
#define BX 32
#define BY 8
#define TW 38   // BX + 6
#define TH 14   // BY + 6

__device__ __forceinline__ void CE(float &x, float &y) {
    float lo = fminf(x, y);
    float hi = fmaxf(x, y);
    x = lo;
    y = hi;
}

// Places min of a[0..N-1] in a[0] and max in a[N-1]; multiset preserved.
template <int N>
__device__ __forceinline__ void minmax_pass(float *a) {
    if constexpr ((N & 1) == 0) {
        // pairwise: mins land in even slots, maxs in odd slots
        #pragma unroll
        for (int j = 0; j < N / 2; j++) CE(a[2 * j], a[2 * j + 1]);
        // min chain over even slots into a[0]
        #pragma unroll
        for (int j = 1; j < N / 2; j++) CE(a[0], a[2 * j]);
        // max chain over odd slots into a[N-1]
        #pragma unroll
        for (int j = 0; j < N / 2 - 1; j++) CE(a[2 * j + 1], a[N - 1]);
    } else {
        // pairwise over first N-1; a[N-1] is the leftover
        #pragma unroll
        for (int j = 0; j < (N - 1) / 2; j++) CE(a[2 * j], a[2 * j + 1]);
        // min chain over even slots, then fold in leftover
        #pragma unroll
        for (int j = 1; j < (N - 1) / 2; j++) CE(a[0], a[2 * j]);
        CE(a[0], a[N - 1]);   // a[0]=global min; a[N-1] only ever grows here
        // max chain over odd slots into a[N-1]
        #pragma unroll
        for (int j = 0; j < (N - 1) / 2; j++) CE(a[2 * j + 1], a[N - 1]);
    }
}

// Iteration T (0..22): set size is 26-T. Discard min/max, overwrite a[0]
// with window element (26+T), implicit discard of a[26-T-1] by shrinking.
template <int T>
__device__ __forceinline__ void forgetful_steps(float *a, const float *tp) {
    if constexpr (T < 23) {
        minmax_pass<26 - T>(a);
        constexpr int w = 26 + T;
        a[0] = tp[(w / 7) * TW + (w % 7)];
        forgetful_steps<T + 1>(a, tp);
    }
}

__global__ __launch_bounds__(BX * BY)
void median7_kernel(const float *__restrict__ in, float *__restrict__ out) {
    __shared__ float tile[TH * TW];

    const int bc  = blockIdx.z;                 // fused batch*channel
    const int ox0 = blockIdx.x * BX;
    const int oy0 = blockIdx.y * BY;
    const int tid = threadIdx.y * BX + threadIdx.x;

    const float *img = in + (size_t)bc * IMG_H * IMG_W;

    // Cooperative load of (BY+6) x (BX+6) tile with zero padding.
    for (int i = tid; i < TH * TW; i += BX * BY) {
        const int r = i / TW;
        const int c = i - r * TW;
        const int gy = oy0 - 3 + r;
        const int gx = ox0 - 3 + c;
        float v = 0.0f;
        if ((unsigned)gy < (unsigned)IMG_H && (unsigned)gx < (unsigned)IMG_W)
            v = img[gy * IMG_W + gx];
        tile[i] = v;
    }
    __syncthreads();

    // Window top-left for this thread inside the tile.
    const float *tp = tile + threadIdx.y * TW + threadIdx.x;

    float a[26];
    #pragma unroll
    for (int w = 0; w < 26; w++)
        a[w] = tp[(w / 7) * TW + (w % 7)];

    forgetful_steps<0>(a, tp);

    // 3 survivors: 23 provably-below and 23 provably-above discarded,
    // so the global median is the middle of a[0..2].
    CE(a[0], a[1]);
    CE(a[0], a[2]);
    CE(a[1], a[2]);

    out[(size_t)bc * IMG_H * IMG_W + (oy0 + threadIdx.y) * IMG_W +
        (ox0 + threadIdx.x)] = a[1];
}

extern "C" void kernel_launch(void *const *d_in, const int *in_sizes, int n_in,
                              void *d_out, int out_size) {
    const float *img = (const float *)d_in[0];
    float *out = (float *)d_out;

    dim3 block(BX, BY);
    dim3 grid(IMG_W / BX, IMG_H / BY, 24);  // 24 = 8 batches * 3 channels
    median7_kernel<<<grid, block>>>(img, out);
}

// round 2
// speedup vs baseline: 1.5820x; 1.5820x over previous
#include <cuda_runtime.h>

// 7x7 exact median blur, zero padding, NCHW 8x3x512x512 fp32.
//
// Strategy (alu-pipe bound -> minimize compare-exchanges):
//  1. Sort each vertical 7-column once (shared across 7 horizontal windows),
//     amortized ~17.5 CE/output via smem.
//  2. Per output, sort the 7 rows of the column-sorted 7x7 window (112 CE).
//     Shearsort lemma: row sorting preserves column sortedness -> matrix is
//     both-ways sorted.
//  3. Both-sorted prune: cell (u,v) 1-based has u*v-1 certified <= and
//     (8-u)(8-v)-1 certified >=. Cells with u*v>=26 are above the median,
//     (8-u)(8-v)>=26 below: 10+10 discards, 29 candidates remain; the
//     median of 49 = rank 15 of the 29 = median of 29.
//  4. Forgetful selection for median-of-29: start 16, stream 13 (175 CE).
// Total ~305 CE/pixel vs 480 for plain forgetful-49.

#define IMG_H 512
#define IMG_W 512
#define BX 64
#define BY 4
#define NT (BX * BY)      // 256 threads
#define TW (BX + 6)       // 70
#define TH (BY + 6)       // 10
#define NCOL (TW * BY)    // 280 column sorts per block

__device__ __forceinline__ void CE(float &x, float &y) {
    float lo = fminf(x, y);
    float hi = fmaxf(x, y);
    x = lo;
    y = hi;
}

// 16-CE sorter for 7 elements: Batcher odd-even mergesort for 8 with wire 7
// pinned to +inf (the 3 CEs touching wire 7 become no-ops and are removed).
__device__ __forceinline__ void sort7(float v[7]) {
    CE(v[0], v[1]); CE(v[2], v[3]); CE(v[4], v[5]);
    CE(v[0], v[2]); CE(v[1], v[3]); CE(v[4], v[6]);
    CE(v[1], v[2]); CE(v[5], v[6]);
    CE(v[0], v[4]); CE(v[1], v[5]); CE(v[2], v[6]);
    CE(v[2], v[4]); CE(v[3], v[5]);
    CE(v[1], v[2]); CE(v[3], v[4]); CE(v[5], v[6]);
}

// Places min of a[0..N-1] in a[0] and max in a[N-1]; multiset preserved.
template <int N>
__device__ __forceinline__ void minmax_pass(float *a) {
    if constexpr ((N & 1) == 0) {
        #pragma unroll
        for (int j = 0; j < N / 2; j++) CE(a[2 * j], a[2 * j + 1]);
        #pragma unroll
        for (int j = 1; j < N / 2; j++) CE(a[0], a[2 * j]);
        #pragma unroll
        for (int j = 0; j < N / 2 - 1; j++) CE(a[2 * j + 1], a[N - 1]);
    } else {
        #pragma unroll
        for (int j = 0; j < (N - 1) / 2; j++) CE(a[2 * j], a[2 * j + 1]);
        #pragma unroll
        for (int j = 1; j < (N - 1) / 2; j++) CE(a[0], a[2 * j]);
        CE(a[0], a[N - 1]);
        #pragma unroll
        for (int j = 0; j < (N - 1) / 2; j++) CE(a[2 * j + 1], a[N - 1]);
    }
}

// Forgetful selection: median (rank 15) of the 29 candidates in c[].
// Working set starts at 16 = ceil(29/2)+1; stream c[16..28].
template <int T>
__device__ __forceinline__ void forgetful29(float *a, const float *c) {
    if constexpr (T < 13) {
        minmax_pass<16 - T>(a);
        a[0] = c[16 + T];
        forgetful29<T + 1>(a, c);
    }
}

__global__ __launch_bounds__(NT)
void median7_kernel(const float *__restrict__ in, float *__restrict__ out) {
    __shared__ float tile[TH * TW];
    __shared__ float scol[7 * BY * TW];  // scol[p][ry][x]: p-th smallest of column

    const int bc  = blockIdx.z;
    const int ox0 = blockIdx.x * BX;
    const int oy0 = blockIdx.y * BY;
    const int tx  = threadIdx.x;
    const int ty  = threadIdx.y;
    const int tid = ty * BX + tx;

    const float *img = in + (size_t)bc * IMG_H * IMG_W;

    // Phase A: load (BY+6) x (BX+6) input tile with zero padding.
    #pragma unroll
    for (int i = tid; i < TH * TW; i += NT) {
        const int r = i / TW;
        const int c = i - r * TW;
        const int gy = oy0 - 3 + r;
        const int gx = ox0 - 3 + c;
        float v = 0.0f;
        if ((unsigned)gy < (unsigned)IMG_H && (unsigned)gx < (unsigned)IMG_W)
            v = img[gy * IMG_W + gx];
        tile[i] = v;
    }
    __syncthreads();

    // Phase B: sort every needed vertical 7-column once.
    // Column (ry, x) covers tile rows ry..ry+6 and serves outputs in row ry.
    for (int k = tid; k < NCOL; k += NT) {
        const int x  = k % TW;
        const int ry = k / TW;
        float v[7];
        #pragma unroll
        for (int i = 0; i < 7; i++) v[i] = tile[(ry + i) * TW + x];
        sort7(v);
        #pragma unroll
        for (int i = 0; i < 7; i++) scol[(i * BY + ry) * TW + x] = v[i];
    }
    __syncthreads();

    // Phase C: per-output row sort of the column-sorted window + prune + select.
    const float *sp = scol + ty * TW + tx;  // row i elem j at sp[i*BY*TW + j]

    float c[29];
    // Candidate keep-ranges per row i (0-based): [lo_i, hi_i]
    //   i: 0->[4,6] 1->[3,6] 2->[2,6] 3->[1,5] 4->[0,4] 5->[0,3] 6->[0,2]
    {
        float r[7];
        #pragma unroll
        for (int j = 0; j < 7; j++) r[j] = sp[0 * BY * TW + j];
        sort7(r);
        c[0] = r[4]; c[1] = r[5]; c[2] = r[6];
    }
    {
        float r[7];
        #pragma unroll
        for (int j = 0; j < 7; j++) r[j] = sp[1 * BY * TW + j];
        sort7(r);
        c[3] = r[3]; c[4] = r[4]; c[5] = r[5]; c[6] = r[6];
    }
    {
        float r[7];
        #pragma unroll
        for (int j = 0; j < 7; j++) r[j] = sp[2 * BY * TW + j];
        sort7(r);
        c[7] = r[2]; c[8] = r[3]; c[9] = r[4]; c[10] = r[5]; c[11] = r[6];
    }
    {
        float r[7];
        #pragma unroll
        for (int j = 0; j < 7; j++) r[j] = sp[3 * BY * TW + j];
        sort7(r);
        c[12] = r[1]; c[13] = r[2]; c[14] = r[3]; c[15] = r[4]; c[16] = r[5];
    }
    {
        float r[7];
        #pragma unroll
        for (int j = 0; j < 7; j++) r[j] = sp[4 * BY * TW + j];
        sort7(r);
        c[17] = r[0]; c[18] = r[1]; c[19] = r[2]; c[20] = r[3]; c[21] = r[4];
    }
    {
        float r[7];
        #pragma unroll
        for (int j = 0; j < 7; j++) r[j] = sp[5 * BY * TW + j];
        sort7(r);
        c[22] = r[0]; c[23] = r[1]; c[24] = r[2]; c[25] = r[3];
    }
    {
        float r[7];
        #pragma unroll
        for (int j = 0; j < 7; j++) r[j] = sp[6 * BY * TW + j];
        sort7(r);
        c[26] = r[0]; c[27] = r[1]; c[28] = r[2];
    }

    // Forgetful selection: median of the 29 candidates.
    float a[16];
    #pragma unroll
    for (int w = 0; w < 16; w++) a[w] = c[w];
    forgetful29<0>(a, c);

    // 3 survivors; median = middle.
    CE(a[0], a[1]);
    CE(a[0], a[2]);
    CE(a[1], a[2]);

    out[(size_t)bc * IMG_H * IMG_W + (oy0 + ty) * IMG_W + (ox0 + tx)] = a[1];
}

extern "C" void kernel_launch(void *const *d_in, const int *in_sizes, int n_in,
                              void *d_out, int out_size) {
    const float *img = (const float *)d_in[0];
    float *out = (float *)d_out;

    dim3 block(BX, BY);
    dim3 grid(IMG_W / BX, IMG_H / BY, 24);  // 24 = 8 batches * 3 channels
    median7_kernel<<<grid, block>>>(img, out);
}

// round 3
// speedup vs baseline: 2.9638x; 1.8735x over previous
#include <cuda_runtime.h>
#include <cuda_fp16.h>

// 7x7 exact-rank median blur, zero padding, NCHW 8x3x512x512 fp32.
//
// Alu-pipe bound -> minimize compare-exchange INSTRUCTIONS:
//   * Same algorithm as R2 (column sorts shared via smem, row sorts ->
//     both-ways-sorted prune to 29 candidates, forgetful selection).
//   * NEW: process TWO images per block packed into half2 lanes; every
//     compare-exchange is one HMNMX2 pair handling 2 pixels -> per-pixel
//     alu instruction count halves.
//   * Precision: fp16 rounding is monotone, so the selected median is the
//     rounding of an element tied with the true median; elementwise rel
//     err <= 2^-11 ~ 4.9e-4 < 1e-3. Pre-scale by 2^10 (exact) to keep all
//     values out of fp16-subnormal range; un-scale output (exact).

#define IMG_H 512
#define IMG_W 512
#define BX 64
#define BY 4
#define NT (BX * BY)      // 256 threads
#define TW (BX + 6)       // 70
#define TH (BY + 6)       // 10
#define NCOL (TW * BY)    // 280 column sorts per block
#define SCALE 1024.0f
#define INV_SCALE (1.0f / 1024.0f)

typedef __half2 h2;

__device__ __forceinline__ void CE(h2 &x, h2 &y) {
    h2 lo = __hmin2(x, y);
    h2 hi = __hmax2(x, y);
    x = lo;
    y = hi;
}

// 16-CE sorter for 7 elements (Batcher-8 with wire 7 pinned to +inf).
__device__ __forceinline__ void sort7(h2 v[7]) {
    CE(v[0], v[1]); CE(v[2], v[3]); CE(v[4], v[5]);
    CE(v[0], v[2]); CE(v[1], v[3]); CE(v[4], v[6]);
    CE(v[1], v[2]); CE(v[5], v[6]);
    CE(v[0], v[4]); CE(v[1], v[5]); CE(v[2], v[6]);
    CE(v[2], v[4]); CE(v[3], v[5]);
    CE(v[1], v[2]); CE(v[3], v[4]); CE(v[5], v[6]);
}

// Places min of a[0..N-1] in a[0] and max in a[N-1]; multiset preserved.
template <int N>
__device__ __forceinline__ void minmax_pass(h2 *a) {
    if constexpr ((N & 1) == 0) {
        #pragma unroll
        for (int j = 0; j < N / 2; j++) CE(a[2 * j], a[2 * j + 1]);
        #pragma unroll
        for (int j = 1; j < N / 2; j++) CE(a[0], a[2 * j]);
        #pragma unroll
        for (int j = 0; j < N / 2 - 1; j++) CE(a[2 * j + 1], a[N - 1]);
    } else {
        #pragma unroll
        for (int j = 0; j < (N - 1) / 2; j++) CE(a[2 * j], a[2 * j + 1]);
        #pragma unroll
        for (int j = 1; j < (N - 1) / 2; j++) CE(a[0], a[2 * j]);
        CE(a[0], a[N - 1]);
        #pragma unroll
        for (int j = 0; j < (N - 1) / 2; j++) CE(a[2 * j + 1], a[N - 1]);
    }
}

// Forgetful selection: median (rank 15) of the 29 candidates in c[].
template <int T>
__device__ __forceinline__ void forgetful29(h2 *a, const h2 *c) {
    if constexpr (T < 13) {
        minmax_pass<16 - T>(a);
        a[0] = c[16 + T];
        forgetful29<T + 1>(a, c);
    }
}

__global__ __launch_bounds__(NT)
void median7_kernel(const float *__restrict__ in, float *__restrict__ out) {
    __shared__ h2 tile[TH * TW];
    __shared__ h2 scol[7 * BY * TW];  // scol[p][ry][x]: p-th smallest of column

    const int bz  = blockIdx.z;                 // image PAIR index (0..11)
    const int ox0 = blockIdx.x * BX;
    const int oy0 = blockIdx.y * BY;
    const int tx  = threadIdx.x;
    const int ty  = threadIdx.y;
    const int tid = ty * BX + tx;

    const size_t plane = (size_t)IMG_H * IMG_W;
    const float *imgA = in + (size_t)(2 * bz) * plane;
    const float *imgB = imgA + plane;

    // Phase A: load (BY+6) x (BX+6) tiles of both images, pack to half2.
    #pragma unroll
    for (int i = tid; i < TH * TW; i += NT) {
        const int r = i / TW;
        const int c = i - r * TW;
        const int gy = oy0 - 3 + r;
        const int gx = ox0 - 3 + c;
        float va = 0.0f, vb = 0.0f;
        if ((unsigned)gy < (unsigned)IMG_H && (unsigned)gx < (unsigned)IMG_W) {
            const int off = gy * IMG_W + gx;
            va = imgA[off];
            vb = imgB[off];
        }
        tile[i] = __floats2half2_rn(va * SCALE, vb * SCALE);
    }
    __syncthreads();

    // Phase B: sort every needed vertical 7-column once (both lanes at once).
    for (int k = tid; k < NCOL; k += NT) {
        const int x  = k % TW;
        const int ry = k / TW;
        h2 v[7];
        #pragma unroll
        for (int i = 0; i < 7; i++) v[i] = tile[(ry + i) * TW + x];
        sort7(v);
        #pragma unroll
        for (int i = 0; i < 7; i++) scol[(i * BY + ry) * TW + x] = v[i];
    }
    __syncthreads();

    // Phase C: row sorts of the column-sorted window -> both-ways sorted
    // matrix -> 29-candidate prune -> forgetful selection.
    const h2 *sp = scol + ty * TW + tx;  // row i elem j at sp[i*BY*TW + j]

    h2 c[29];
    {
        h2 r[7];
        #pragma unroll
        for (int j = 0; j < 7; j++) r[j] = sp[0 * BY * TW + j];
        sort7(r);
        c[0] = r[4]; c[1] = r[5]; c[2] = r[6];
    }
    {
        h2 r[7];
        #pragma unroll
        for (int j = 0; j < 7; j++) r[j] = sp[1 * BY * TW + j];
        sort7(r);
        c[3] = r[3]; c[4] = r[4]; c[5] = r[5]; c[6] = r[6];
    }
    {
        h2 r[7];
        #pragma unroll
        for (int j = 0; j < 7; j++) r[j] = sp[2 * BY * TW + j];
        sort7(r);
        c[7] = r[2]; c[8] = r[3]; c[9] = r[4]; c[10] = r[5]; c[11] = r[6];
    }
    {
        h2 r[7];
        #pragma unroll
        for (int j = 0; j < 7; j++) r[j] = sp[3 * BY * TW + j];
        sort7(r);
        c[12] = r[1]; c[13] = r[2]; c[14] = r[3]; c[15] = r[4]; c[16] = r[5];
    }
    {
        h2 r[7];
        #pragma unroll
        for (int j = 0; j < 7; j++) r[j] = sp[4 * BY * TW + j];
        sort7(r);
        c[17] = r[0]; c[18] = r[1]; c[19] = r[2]; c[20] = r[3]; c[21] = r[4];
    }
    {
        h2 r[7];
        #pragma unroll
        for (int j = 0; j < 7; j++) r[j] = sp[5 * BY * TW + j];
        sort7(r);
        c[22] = r[0]; c[23] = r[1]; c[24] = r[2]; c[25] = r[3];
    }
    {
        h2 r[7];
        #pragma unroll
        for (int j = 0; j < 7; j++) r[j] = sp[6 * BY * TW + j];
        sort7(r);
        c[26] = r[0]; c[27] = r[1]; c[28] = r[2];
    }

    h2 a[16];
    #pragma unroll
    for (int w = 0; w < 16; w++) a[w] = c[w];
    forgetful29<0>(a, c);

    CE(a[0], a[1]);
    CE(a[0], a[2]);
    CE(a[1], a[2]);

    const float2 f = __half22float2(a[1]);
    const size_t o = (size_t)(oy0 + ty) * IMG_W + (ox0 + tx);
    out[(size_t)(2 * bz) * plane + o] = f.x * INV_SCALE;
    out[(size_t)(2 * bz + 1) * plane + o] = f.y * INV_SCALE;
}

extern "C" void kernel_launch(void *const *d_in, const int *in_sizes, int n_in,
                              void *d_out, int out_size) {
    const float *img = (const float *)d_in[0];
    float *out = (float *)d_out;

    dim3 block(BX, BY);
    dim3 grid(IMG_W / BX, IMG_H / BY, 12);  // 12 pairs of the 24 images
    median7_kernel<<<grid, block>>>(img, out);
}